// round 6
// baseline (speedup 1.0000x reference)
#include <cuda_runtime.h>
#include <cstdint>

// GraphConvolution: y = relu( (D^-1 A) x W^T + b )
// A = tridiagonal + self loops over 55 nodes, row-normalized.
// x: [16384, 55, 48] fp32, W: [48,48] fp32 (y[o] = sum_f ax[f]*W[o][f]), b: [48].
//
// One block = NB=4 batch items. Threads 0..219 each compute one (batch,node)
// output row: 3-point neighbor average (from padded smem), then a 48x48
// matvec using packed fma.rn.f32x2 against W^T broadcast from smem.

#define NB      4
#define NNODES  55
#define NF      48
#define ROWP    52          // padded smem row stride (floats): conflict-free LDS.128
#define THREADS 224
#define ROWS    (NB * NNODES)   // 220 active threads

#define SX_FLOATS  (NB * NNODES * ROWP)          // 11440
#define SMEM_FLOATS (SX_FLOATS + NF * NF + NF)   // 13792
#define SMEM_BYTES  (SMEM_FLOATS * 4)            // 55168

__global__ __launch_bounds__(THREADS)
void gconv_f32x2_kernel(const float* __restrict__ x,
                        const float* __restrict__ W,
                        const float* __restrict__ bias,
                        float* __restrict__ out)
{
    extern __shared__ float smem[];
    float* sx  = smem;                 // [NB*NNODES][ROWP]
    float* sWt = smem + SX_FLOATS;     // [NF][NF]  Wt[f][o] = W[o][f]
    float* sb  = sWt + NF * NF;        // [NF]

    const int t = threadIdx.x;
    const size_t base = (size_t)blockIdx.x * (NB * NNODES * NF);

    // ---- stage x (coalesced global float4 -> padded smem rows) ----
    {
        const float4* xg4 = (const float4*)(x + base);
        #pragma unroll 4
        for (int c = t; c < NB * NNODES * (NF / 4); c += THREADS) {
            int row = c / (NF / 4);
            int p   = c % (NF / 4);
            *(float4*)(sx + row * ROWP + p * 4) = xg4[c];
        }
    }
    // ---- stage W transposed ----
    for (int i = t; i < NF * NF; i += THREADS) {
        int o = i / NF, f = i % NF;
        sWt[f * NF + o] = W[i];
    }
    if (t < NF) sb[t] = bias[t];
    __syncthreads();

    if (t < ROWS) {
        const int node = t % NNODES;
        const float* xr = sx + t * ROWP;
        const float* xm = xr - ((node > 0)          ? ROWP : 0);
        const float* xp = xr + ((node < NNODES - 1) ? ROWP : 0);
        const float wm = (node > 0)          ? 1.0f : 0.0f;
        const float wp = (node < NNODES - 1) ? 1.0f : 0.0f;
        const float scale = 1.0f / (1.0f + wm + wp);

        // 24 packed-f32x2 accumulators = all 48 outputs, init with bias pairs
        unsigned long long acc[NF / 2];
        #pragma unroll
        for (int j = 0; j < NF / 2; j++) {
            float b0 = sb[2 * j], b1 = sb[2 * j + 1];
            asm("mov.b64 %0, {%1, %2};" : "=l"(acc[j]) : "f"(b0), "f"(b1));
        }

        const unsigned swt_base = (unsigned)__cvta_generic_to_shared(sWt);

        #pragma unroll 3
        for (int f4 = 0; f4 < NF / 4; f4++) {
            float4 vm = *(const float4*)(xm + f4 * 4);
            float4 vc = *(const float4*)(xr + f4 * 4);
            float4 vp = *(const float4*)(xp + f4 * 4);
            float av[4];
            av[0] = (vc.x + wm * vm.x + wp * vp.x) * scale;
            av[1] = (vc.y + wm * vm.y + wp * vp.y) * scale;
            av[2] = (vc.z + wm * vm.z + wp * vp.z) * scale;
            av[3] = (vc.w + wm * vm.w + wp * vp.w) * scale;

            #pragma unroll
            for (int u = 0; u < 4; u++) {
                const int f = f4 * 4 + u;
                unsigned long long aa;  // {a, a}
                asm("mov.b64 %0, {%1, %1};" : "=l"(aa) : "f"(av[u]));
                const unsigned wrow = swt_base + f * NF * 4;
                #pragma unroll
                for (int j4 = 0; j4 < NF / 4; j4++) {
                    unsigned long long w01, w23;  // Wt[f][4j4..4j4+3] as two pairs
                    asm("ld.shared.v2.b64 {%0, %1}, [%2];"
                        : "=l"(w01), "=l"(w23) : "r"(wrow + j4 * 16));
                    asm("fma.rn.f32x2 %0, %1, %2, %0;"
                        : "+l"(acc[2 * j4])     : "l"(aa), "l"(w01));
                    asm("fma.rn.f32x2 %0, %1, %2, %0;"
                        : "+l"(acc[2 * j4 + 1]) : "l"(aa), "l"(w23));
                }
            }
        }

        // ---- ReLU + store (float4 per 4 outputs) ----
        float* og = out + base + (size_t)t * NF;
        #pragma unroll
        for (int q = 0; q < NF / 4; q++) {
            float r0, r1, r2, r3;
            asm("mov.b64 {%0, %1}, %2;" : "=f"(r0), "=f"(r1) : "l"(acc[2 * q]));
            asm("mov.b64 {%0, %1}, %2;" : "=f"(r2), "=f"(r3) : "l"(acc[2 * q + 1]));
            float4 v = make_float4(fmaxf(r0, 0.0f), fmaxf(r1, 0.0f),
                                   fmaxf(r2, 0.0f), fmaxf(r3, 0.0f));
            *(float4*)(og + q * 4) = v;
        }
    }
}

extern "C" void kernel_launch(void* const* d_in, const int* in_sizes, int n_in,
                              void* d_out, int out_size)
{
    const float* x = (const float*)d_in[0];   // [16384, 55, 48]
    const float* W = (const float*)d_in[1];   // [48, 48]
    const float* b = (const float*)d_in[2];   // [48]
    float* out = (float*)d_out;               // [16384, 55, 48]

    (void)in_sizes; (void)n_in; (void)out_size;

    cudaFuncSetAttribute(gconv_f32x2_kernel,
                         cudaFuncAttributeMaxDynamicSharedMemorySize, SMEM_BYTES);

    const int nblocks = 16384 / NB;  // 4096, exact
    gconv_f32x2_kernel<<<nblocks, THREADS, SMEM_BYTES>>>(x, W, b, out);
}

// round 8
// speedup vs baseline: 1.3999x; 1.3999x over previous
#include <cuda_runtime.h>
#include <cstdint>

// GraphConvolution: y = relu( (D^-1 A) x W^T + b )
// x: [16384, 55, 48] fp32, W: [48,48], b: [48]. A = tridiagonal+self, row-norm.
//
// One block = 4 batch items = 220 (batch,node) rows. Register tiling:
// thread (rg, og) computes rows 4*rg..4*rg+3  x  outputs 12*og..12*og+11.
// Per f: 3 LDS.128 of W (vs 12 untiled) + shared neighbor rows across the
// 4-row group (6 float4 per 4 f's). 24 packed fma.rn.f32x2 per f.
// Outputs staged through reused sx smem for coalesced global stores.
// Batch-boundary note: row groups straddle batches (55 % 4 != 0); clamped
// neighbor pointers may cross a batch, but those lanes carry weight 0
// (wm/wp derived from node = row % 55), so the values never contribute.

#define NB      4
#define NNODES  55
#define NF      48
#define ROWP    52              // padded smem row stride (floats)
#define THREADS 224
#define ROWS    (NB * NNODES)   // 220

#define SX_FLOATS   (ROWS * ROWP)                 // 11440
#define SMEM_FLOATS (SX_FLOATS + NF * NF + NF)    // 13792
#define SMEM_BYTES  (SMEM_FLOATS * 4)             // 55168

__global__ __launch_bounds__(THREADS, 2)
void gconv_tiled_kernel(const float* __restrict__ x,
                        const float* __restrict__ W,
                        const float* __restrict__ bias,
                        float* __restrict__ out)
{
    extern __shared__ float smem[];
    float* sx  = smem;                 // [220][ROWP], reused for output staging
    float* sWt = smem + SX_FLOATS;     // [NF][NF]  Wt[f][o] = W[o][f]
    float* sb  = sWt + NF * NF;        // [NF]

    const int t = threadIdx.x;
    const size_t base = (size_t)blockIdx.x * (ROWS * NF);

    // ---- phase 0: stage x (coalesced float4 -> padded smem rows) ----
    {
        const float4* xg4 = (const float4*)(x + base);
        #pragma unroll 4
        for (int c = t; c < ROWS * (NF / 4); c += THREADS) {
            int row = c / (NF / 4);
            int p   = c % (NF / 4);
            *(float4*)(sx + row * ROWP + p * 4) = xg4[c];
        }
    }
    for (int i = t; i < NF * NF; i += THREADS) {
        int o = i / NF, f = i % NF;
        sWt[f * NF + o] = W[i];
    }
    if (t < NF) sb[t] = bias[t];
    __syncthreads();

    unsigned long long acc[4][6];      // [row][output-pair], persists across sync

    const int og = t & 3;              // output group: outputs 12*og..12*og+11
    const int rg = t >> 2;             // row group:    rows    4*rg..4*rg+3
    const int r0 = rg * 4;

    if (t < ROWS) {
        // per-row neighbor weights
        float wm[4], wp[4], sc[4];
        #pragma unroll
        for (int i = 0; i < 4; i++) {
            int node = (r0 + i) % NNODES;
            wm[i] = (node > 0)          ? 1.0f : 0.0f;
            wp[i] = (node < NNODES - 1) ? 1.0f : 0.0f;
            sc[i] = 1.0f / (1.0f + wm[i] + wp[i]);
        }

        // init accumulators with bias pairs
        #pragma unroll
        for (int j = 0; j < 6; j++) {
            float b0 = sb[og * 12 + 2 * j], b1 = sb[og * 12 + 2 * j + 1];
            unsigned long long bb;
            asm("mov.b64 %0, {%1, %2};" : "=l"(bb) : "f"(b0), "f"(b1));
            #pragma unroll
            for (int i = 0; i < 4; i++) acc[i][j] = bb;
        }

        // 6 source rows r0-1 .. r0+4 (clamped; out-of-range reads get weight 0)
        const float* xr[6];
        #pragma unroll
        for (int j = 0; j < 6; j++) {
            int rr = r0 - 1 + j;
            rr = rr < 0 ? 0 : (rr > ROWS - 1 ? ROWS - 1 : rr);
            xr[j] = sx + rr * ROWP;
        }

        const unsigned swt = (unsigned)__cvta_generic_to_shared(sWt) + og * 12 * 4;

        #pragma unroll 1
        for (int f4 = 0; f4 < NF / 4; f4++) {
            float4 v[6];
            #pragma unroll
            for (int j = 0; j < 6; j++) v[j] = *(const float4*)(xr[j] + f4 * 4);

            #pragma unroll
            for (int u = 0; u < 4; u++) {
                const int f = f4 * 4 + u;
                // banded average for the 4 rows at feature f
                float av[4];
                #pragma unroll
                for (int i = 0; i < 4; i++) {
                    float m = ((const float*)&v[i])[u];
                    float c = ((const float*)&v[i + 1])[u];
                    float p = ((const float*)&v[i + 2])[u];
                    av[i] = (c + wm[i] * m + wp[i] * p) * sc[i];
                }
                // 12 W values for this f (3 x LDS.128, conflict-free across og)
                unsigned long long wv[6];
                const unsigned a = swt + f * (NF * 4);
                asm("ld.shared.v2.b64 {%0, %1}, [%2];"
                    : "=l"(wv[0]), "=l"(wv[1]) : "r"(a));
                asm("ld.shared.v2.b64 {%0, %1}, [%2];"
                    : "=l"(wv[2]), "=l"(wv[3]) : "r"(a + 16));
                asm("ld.shared.v2.b64 {%0, %1}, [%2];"
                    : "=l"(wv[4]), "=l"(wv[5]) : "r"(a + 32));

                #pragma unroll
                for (int i = 0; i < 4; i++) {
                    unsigned long long aa;   // {a, a}
                    asm("mov.b64 %0, {%1, %1};" : "=l"(aa) : "f"(av[i]));
                    #pragma unroll
                    for (int j = 0; j < 6; j++)
                        asm("fma.rn.f32x2 %0, %1, %2, %0;"
                            : "+l"(acc[i][j]) : "l"(aa), "l"(wv[j]));
                }
            }
        }
    }
    __syncthreads();   // all sx reads complete -> safe to reuse as output stage

    // ---- stage ReLU'd outputs into sx (conflict-free STS.128) ----
    if (t < ROWS) {
        #pragma unroll
        for (int i = 0; i < 4; i++) {
            float* dst = sx + (r0 + i) * ROWP + og * 12;
            #pragma unroll
            for (int q = 0; q < 3; q++) {
                float r0_, r1_, r2_, r3_;
                asm("mov.b64 {%0, %1}, %2;" : "=f"(r0_), "=f"(r1_) : "l"(acc[i][2 * q]));
                asm("mov.b64 {%0, %1}, %2;" : "=f"(r2_), "=f"(r3_) : "l"(acc[i][2 * q + 1]));
                float4 vv = make_float4(fmaxf(r0_, 0.0f), fmaxf(r1_, 0.0f),
                                        fmaxf(r2_, 0.0f), fmaxf(r3_, 0.0f));
                *(float4*)(dst + q * 4) = vv;
            }
        }
    }
    __syncthreads();

    // ---- coalesced store (full 32B sectors) ----
    {
        float4* og4 = (float4*)(out + base);
        #pragma unroll 4
        for (int c = t; c < ROWS * (NF / 4); c += THREADS) {
            int row = c / (NF / 4);
            int p   = c % (NF / 4);
            og4[c] = *(const float4*)(sx + row * ROWP + p * 4);
        }
    }
}

extern "C" void kernel_launch(void* const* d_in, const int* in_sizes, int n_in,
                              void* d_out, int out_size)
{
    const float* x = (const float*)d_in[0];   // [16384, 55, 48]
    const float* W = (const float*)d_in[1];   // [48, 48]
    const float* b = (const float*)d_in[2];   // [48]
    float* out = (float*)d_out;               // [16384, 55, 48]

    (void)in_sizes; (void)n_in; (void)out_size;

    cudaFuncSetAttribute(gconv_tiled_kernel,
                         cudaFuncAttributeMaxDynamicSharedMemorySize, SMEM_BYTES);

    const int nblocks = 16384 / NB;  // 4096, exact
    gconv_tiled_kernel<<<nblocks, THREADS, SMEM_BYTES>>>(x, W, b, out);
}

// round 9
// speedup vs baseline: 1.5666x; 1.1191x over previous
#include <cuda_runtime.h>
#include <cstdint>

// GraphConvolution: y = relu( (D^-1 A) x W^T + b )
// x: [16384, 55, 48] fp32, W: [48,48], b: [48]. A = tridiagonal+self, row-norm.
//
// One block = 6 batch items = 330 rows (last block: 4 batches / 220 rows).
// Thread (rg, og) computes rows 6*rg..6*rg+5  x  outputs 12*og..12*og+11.
// Unscaled accumulation s = c + wm*m + wp*p; degree scale sc folded into the
// final packed FMA with bias: y = relu(sc*acc + b). 36 packed f32x2 MACs per f
// per thread; 3 LDS.128 of W per f shared across 6 rows.

#define NB       6
#define NNODES   55
#define NF       48
#define ROWP     52              // padded smem row stride (floats)
#define THREADS  224
#define ROWSMAX  (NB * NNODES)   // 330
#define NBATCHES 16384

#define SX_FLOATS   (ROWSMAX * ROWP)               // 17160
#define SMEM_FLOATS (SX_FLOATS + NF * NF + NF)     // 19512
#define SMEM_BYTES  (SMEM_FLOATS * 4)              // 78048

__global__ __launch_bounds__(THREADS, 2)
void gconv_r6_kernel(const float* __restrict__ x,
                     const float* __restrict__ W,
                     const float* __restrict__ bias,
                     float* __restrict__ out)
{
    extern __shared__ float smem[];
    float* sx  = smem;                 // [<=330][ROWP], reused for output staging
    float* sWt = smem + SX_FLOATS;     // [NF][NF]  Wt[f][o] = W[o][f]
    float* sb  = sWt + NF * NF;        // [NF]

    const int t   = threadIdx.x;
    const int bid = blockIdx.x;
    int batches = NBATCHES - bid * NB;
    if (batches > NB) batches = NB;            // tail block has 4
    const int rows_cta = batches * NNODES;
    const int elems4   = rows_cta * (NF / 4);
    const size_t base  = (size_t)bid * (NB * NNODES * NF);

    // ---- stage x (coalesced float4 -> padded smem rows) ----
    {
        const float4* xg4 = (const float4*)(x + base);
        for (int c = t; c < elems4; c += THREADS) {
            int row = c / (NF / 4), p = c % (NF / 4);
            *(float4*)(sx + row * ROWP + p * 4) = xg4[c];
        }
    }
    for (int i = t; i < NF * NF; i += THREADS) {
        int o = i / NF, f = i % NF;
        sWt[f * NF + o] = W[i];
    }
    if (t < NF) sb[t] = bias[t];
    __syncthreads();

    const int og = t & 3;              // outputs 12*og..12*og+11
    const int rg = t >> 2;             // rows    6*rg..6*rg+5
    const int r0 = rg * 6;
    const bool active = (t < 220) && (r0 < rows_cta);

    unsigned long long acc[6][6];      // [row][output-pair]

    if (active) {
        float wm[6], wp[6];
        #pragma unroll
        for (int i = 0; i < 6; i++) {
            int node = (r0 + i) % NNODES;
            wm[i] = (node > 0)          ? 1.0f : 0.0f;
            wp[i] = (node < NNODES - 1) ? 1.0f : 0.0f;
        }
        // neighbor rows r0-1 .. r0+6 as byte offsets (clamped; clamp-overreach
        // always lands on a weight-0 lane, incl. across batch boundaries)
        unsigned offs[8];
        #pragma unroll
        for (int j = 0; j < 8; j++) {
            int rr = r0 - 1 + j;
            rr = rr < 0 ? 0 : (rr > rows_cta - 1 ? rows_cta - 1 : rr);
            offs[j] = (unsigned)(rr * (ROWP * 4));
        }
        const char* sxb = (const char*)sx;

        #pragma unroll
        for (int i = 0; i < 6; i++)
            #pragma unroll
            for (int j = 0; j < 6; j++) acc[i][j] = 0ULL;

        const unsigned swt = (unsigned)__cvta_generic_to_shared(sWt) + og * 12 * 4;

        #pragma unroll 1
        for (int f4 = 0; f4 < NF / 4; f4++) {
            const int fb = f4 * 16;
            float av[4][6];            // [u][row] unscaled banded sums
            {   // rows r0-1 .. r0+3 -> av rows 0..2
                float4 va[5];
                #pragma unroll
                for (int q = 0; q < 5; q++)
                    va[q] = *(const float4*)(sxb + offs[q] + fb);
                #pragma unroll
                for (int i = 0; i < 3; i++)
                    #pragma unroll
                    for (int u = 0; u < 4; u++) {
                        float m = ((const float*)&va[i])[u];
                        float c = ((const float*)&va[i + 1])[u];
                        float p = ((const float*)&va[i + 2])[u];
                        av[u][i] = fmaf(wp[i], p, fmaf(wm[i], m, c));
                    }
            }
            {   // rows r0+2 .. r0+6 -> av rows 3..5
                float4 vb[5];
                #pragma unroll
                for (int q = 0; q < 5; q++)
                    vb[q] = *(const float4*)(sxb + offs[q + 3] + fb);
                #pragma unroll
                for (int i = 3; i < 6; i++)
                    #pragma unroll
                    for (int u = 0; u < 4; u++) {
                        float m = ((const float*)&vb[i - 3])[u];
                        float c = ((const float*)&vb[i - 2])[u];
                        float p = ((const float*)&vb[i - 1])[u];
                        av[u][i] = fmaf(wp[i], p, fmaf(wm[i], m, c));
                    }
            }
            const unsigned wbase = swt + f4 * 4 * (NF * 4);
            #pragma unroll
            for (int u = 0; u < 4; u++) {
                unsigned long long wv[6];
                const unsigned a = wbase + u * (NF * 4);
                asm("ld.shared.v2.b64 {%0,%1}, [%2];"
                    : "=l"(wv[0]), "=l"(wv[1]) : "r"(a));
                asm("ld.shared.v2.b64 {%0,%1}, [%2];"
                    : "=l"(wv[2]), "=l"(wv[3]) : "r"(a + 16));
                asm("ld.shared.v2.b64 {%0,%1}, [%2];"
                    : "=l"(wv[4]), "=l"(wv[5]) : "r"(a + 32));
                #pragma unroll
                for (int i = 0; i < 6; i++) {
                    unsigned long long aa;   // {av, av}
                    asm("mov.b64 %0, {%1,%1};" : "=l"(aa) : "f"(av[u][i]));
                    #pragma unroll
                    for (int j = 0; j < 6; j++)
                        asm("fma.rn.f32x2 %0, %1, %2, %0;"
                            : "+l"(acc[i][j]) : "l"(aa), "l"(wv[j]));
                }
            }
        }

        // ---- fold degree scale + bias: acc = sc*acc + b (packed) ----
        #pragma unroll
        for (int i = 0; i < 6; i++) {
            int node = (r0 + i) % NNODES;
            float sc = (node == 0 || node == NNODES - 1) ? 0.5f : (1.0f / 3.0f);
            unsigned long long ss;
            asm("mov.b64 %0, {%1,%1};" : "=l"(ss) : "f"(sc));
            #pragma unroll
            for (int j = 0; j < 6; j++) {
                float b0 = sb[og * 12 + 2 * j], b1 = sb[og * 12 + 2 * j + 1];
                unsigned long long bb;
                asm("mov.b64 %0, {%1,%2};" : "=l"(bb) : "f"(b0), "f"(b1));
                asm("fma.rn.f32x2 %0, %1, %2, %3;"
                    : "=l"(acc[i][j]) : "l"(acc[i][j]), "l"(ss), "l"(bb));
            }
        }
    }
    __syncthreads();   // all sx reads complete -> safe to reuse as output stage

    // ---- ReLU + stage into sx ----
    if (active) {
        #pragma unroll
        for (int i = 0; i < 6; i++) {
            if (r0 + i < rows_cta) {
                float* dst = sx + (r0 + i) * ROWP + og * 12;
                #pragma unroll
                for (int q = 0; q < 3; q++) {
                    float a0, a1, a2, a3;
                    asm("mov.b64 {%0,%1}, %2;" : "=f"(a0), "=f"(a1) : "l"(acc[i][2 * q]));
                    asm("mov.b64 {%0,%1}, %2;" : "=f"(a2), "=f"(a3) : "l"(acc[i][2 * q + 1]));
                    float4 v = make_float4(fmaxf(a0, 0.0f), fmaxf(a1, 0.0f),
                                           fmaxf(a2, 0.0f), fmaxf(a3, 0.0f));
                    *(float4*)(dst + q * 4) = v;
                }
            }
        }
    }
    __syncthreads();

    // ---- coalesced store ----
    {
        float4* og4 = (float4*)(out + base);
        for (int c = t; c < elems4; c += THREADS) {
            int row = c / (NF / 4), p = c % (NF / 4);
            og4[c] = *(const float4*)(sx + row * ROWP + p * 4);
        }
    }
}

extern "C" void kernel_launch(void* const* d_in, const int* in_sizes, int n_in,
                              void* d_out, int out_size)
{
    const float* x = (const float*)d_in[0];   // [16384, 55, 48]
    const float* W = (const float*)d_in[1];   // [48, 48]
    const float* b = (const float*)d_in[2];   // [48]
    float* out = (float*)d_out;               // [16384, 55, 48]

    (void)in_sizes; (void)n_in; (void)out_size;

    cudaFuncSetAttribute(gconv_r6_kernel,
                         cudaFuncAttributeMaxDynamicSharedMemorySize, SMEM_BYTES);

    const int nblocks = (NBATCHES + NB - 1) / NB;  // 2731 (last block: 4 batches)
    gconv_r6_kernel<<<nblocks, THREADS, SMEM_BYTES>>>(x, W, b, out);
}